// round 14
// baseline (speedup 1.0000x reference)
#include <cuda_runtime.h>
#include <cuda_bf16.h>
#include <cstdint>

// ---------------------------------------------------------------------------
// Residual VQ: B=8, T=4096, D=128, NUM_CB=8, K=1024   (N = 32768 rows)
// out (float32): [0,262144) codes [B,T,8]; [262144,+4194304) quantized; last = loss
//
// mma.sync.m16n8k8 tf32 3-way split + candidate-set exact rescue:
//   Each row's 1024 codes are scored by 8 threads (128 codes each) which keep
//   their local top-2 -> 16 candidates/row in smem. If the global top-2 gap
//   < EPS(5e-4), the row is re-decided over its 16 candidates with the exact
//   fp32 chain proven flip-free in R1/R9. If any thread's 2nd candidate is
//   also inside the window (could hide a 3rd near-tie), full-1024 exact scan.
// ---------------------------------------------------------------------------

#define N_ROWS   32768
#define DIM      128
#define NUM_CB   8
#define KCB      1024
#define M_TILE   128
#define APITCH   132
#define N_CTAS   (N_ROWS / M_TILE)     // 256
#define CODES_SZ (N_ROWS * NUM_CB)
#define QUANT_SZ (N_ROWS * DIM)
#define THREADS  256
#define CHUNK    64
#define CHUNKS_PER_CB 16
#define TILES    (NUM_CB * CHUNKS_PER_CB)   // 128
#define BTILE_F4 4096
#define BTILE_BYTES 65536
#define EPS_GAP  5e-4f

// smem layout (floats)
#define SMF_A    0                     // 16896
#define SMF_B0   16896                 // 16384
#define SMF_B1   33280                 // 16384
#define SMF_WN   49664                 // 1024
#define SMF_RN   50688                 // 128
#define SMF_RP   50816                 // 256
#define SMF_CAND 51072                 // 4096 (= 2048 u64: 128 rows x 8 thr x 2)
#define SMF_KB   55168                 // 1024 ints
#define SMF_MODE 56192                 // 128 ints
#define SMF_LIST 56320                 // 128 ints list + cnt + pad (132)
#define SMF_RK   56452                 // 1 u64
#define SMEM_FLOATS 56454
#define SMEM_BYTES  (SMEM_FLOATS * 4)  // 225816

__device__ double g_loss;
__device__ float  g_wnorm[NUM_CB * KCB];
__device__ __align__(16) float4 g_wf[TILES * BTILE_F4];   // 8MB tf32 frag bits

// ---------------- helpers ----------------
__device__ __forceinline__ unsigned sortf(float f) {
    unsigned u = __float_as_uint(f);
    return u ^ (((int)u >> 31) | 0x80000000u);
}
__device__ __forceinline__ float unsortf(unsigned u) {
    unsigned mask = (unsigned)(((int)(~u)) >> 31) | 0x80000000u;
    return __uint_as_float(u ^ mask);
}
__device__ __forceinline__ void split_tf32(float x, unsigned& h, unsigned& l) {
    unsigned hb; asm("cvt.rna.tf32.f32 %0, %1;" : "=r"(hb) : "f"(x));
    float lf = __fadd_rn(x, -__uint_as_float(hb));
    unsigned lb; asm("cvt.rna.tf32.f32 %0, %1;" : "=r"(lb) : "f"(lf));
    h = hb; l = lb;
}
__device__ __forceinline__ void mma8(float* d, const unsigned* a,
                                     unsigned b0, unsigned b1) {
    asm volatile(
        "mma.sync.aligned.m16n8k8.row.col.f32.tf32.tf32.f32 "
        "{%0,%1,%2,%3}, {%4,%5,%6,%7}, {%8,%9}, {%0,%1,%2,%3};"
        : "+f"(d[0]), "+f"(d[1]), "+f"(d[2]), "+f"(d[3])
        : "r"(a[0]), "r"(a[1]), "r"(a[2]), "r"(a[3]), "r"(b0), "r"(b1));
}
__device__ __forceinline__ void cp_async16(void* sdst, const void* gsrc) {
    unsigned saddr = (unsigned)__cvta_generic_to_shared(sdst);
    asm volatile("cp.async.cg.shared.global [%0], [%1], 16;\n" :: "r"(saddr), "l"(gsrc));
}
__device__ __forceinline__ void cp_commit() { asm volatile("cp.async.commit_group;\n"); }
__device__ __forceinline__ void cp_wait1() { asm volatile("cp.async.wait_group 1;\n"); }
__device__ __forceinline__ void top2_upd(unsigned long long k,
                                         unsigned long long& b1,
                                         unsigned long long& b2) {
    unsigned long long lo = min(k, b1), hi = max(k, b1);
    b1 = lo;
    b2 = min(b2, hi);
}

// ---------------- precompute: wnorm + loss zero ----------------
__global__ void wnorm_kernel(const float* __restrict__ cb) {
    int k = blockIdx.x * blockDim.x + threadIdx.x;
    if (blockIdx.x == 0 && threadIdx.x == 0) g_loss = 0.0;
    if (k >= NUM_CB * KCB) return;
    const float4* p = reinterpret_cast<const float4*>(cb + (size_t)k * DIM);
    float4 s = make_float4(0.f, 0.f, 0.f, 0.f);
#pragma unroll
    for (int i = 0; i < 32; ++i) {
        float4 v = p[i];
        s.x = __fadd_rn(s.x, __fmul_rn(v.x, v.x));
        s.y = __fadd_rn(s.y, __fmul_rn(v.y, v.y));
        s.z = __fadd_rn(s.z, __fmul_rn(v.z, v.z));
        s.w = __fadd_rn(s.w, __fmul_rn(v.w, v.w));
    }
    g_wnorm[k] = __fadd_rn(__fadd_rn(s.x, s.y), __fadd_rn(s.z, s.w));
}

// ---------------- precompute: W fragments (tf32 hi/lo of 2*w) ----------------
__global__ void wfrag_kernel(const float* __restrict__ cb) {
    int idx = blockIdx.x * 256 + threadIdx.x;   // 0..524287
    int lane = idx & 31;
    int kt   = (idx >> 5) & 15;
    int nt   = (idx >> 9) & 7;
    int t    = idx >> 12;
    int cbi = t >> 4, ch = t & 15;
    int code = ch * CHUNK + nt * 8 + (lane >> 2);
    int k    = kt * 8 + (lane & 3);
    const float* w = cb + ((size_t)(cbi * KCB + code)) * DIM + k;
    float w0 = 2.0f * w[0];
    float w1 = 2.0f * w[4];
    unsigned h0, l0, h1, l1;
    split_tf32(w0, h0, l0);
    split_tf32(w1, h1, l1);
    float4 v;
    v.x = __uint_as_float(h0); v.y = __uint_as_float(h1);
    v.z = __uint_as_float(l0); v.w = __uint_as_float(l1);
    g_wf[idx] = v;
}

// ---------------- main kernel ----------------
__global__ void __launch_bounds__(THREADS, 1)
rvq_main(const float* __restrict__ emb, const float* __restrict__ cb,
         float* __restrict__ out) {
    extern __shared__ float sm[];
    float* A_s     = sm + SMF_A;
    float* B0      = sm + SMF_B0;
    float* B1      = sm + SMF_B1;
    float* WN      = sm + SMF_WN;
    float* rownorm = sm + SMF_RN;
    float* rn_part = sm + SMF_RP;
    unsigned long long* CAND = reinterpret_cast<unsigned long long*>(sm + SMF_CAND);
    int*   kbest   = reinterpret_cast<int*>(sm + SMF_KB);
    int*   rowmode = reinterpret_cast<int*>(sm + SMF_MODE);
    int*   list1   = reinterpret_cast<int*>(sm + SMF_LIST);
    int*   cnt1    = list1 + 128;
    unsigned long long* rk = reinterpret_cast<unsigned long long*>(sm + SMF_RK);

    const int tid  = threadIdx.x;
    const int lane = tid & 31;
    const int gid  = lane >> 2;
    const int tig  = lane & 3;
    const int wid  = tid >> 5;
    const int rg   = wid & 3;
    const int chh  = wid >> 2;
    const int row0 = blockIdx.x * M_TILE;

    if (tid == 0) *rk = ~0ull;

    // ---- load A tile ----
    {
        const float4* ev = reinterpret_cast<const float4*>(emb + (size_t)row0 * DIM);
#pragma unroll
        for (int i = 0; i < 16; ++i) {
            int f = tid + i * THREADS;
            int r = f >> 5, d4 = f & 31;
            reinterpret_cast<float4*>(A_s)[r * (APITCH / 4) + d4] = ev[f];
        }
    }

    // ---- prefetch first B chunk ----
    {
        const char* src = reinterpret_cast<const char*>(g_wf);
#pragma unroll
        for (int i = 0; i < 16; ++i) {
            int f = tid + i * THREADS;
            cp_async16(reinterpret_cast<char*>(B0) + (size_t)f * 16,
                       src + (size_t)f * 16);
        }
        cp_commit();
    }
    __syncthreads();

    // ---- initial row norms (half partials, as R1) ----
    {
        int r = tid & 127, h = tid >> 7;
        const float4* a = reinterpret_cast<const float4*>(A_s + r * APITCH + h * 64);
        float4 s = make_float4(0.f, 0.f, 0.f, 0.f);
#pragma unroll
        for (int i = 0; i < 16; ++i) {
            float4 v = a[i];
            s.x = __fadd_rn(s.x, __fmul_rn(v.x, v.x));
            s.y = __fadd_rn(s.y, __fmul_rn(v.y, v.y));
            s.z = __fadd_rn(s.z, __fmul_rn(v.z, v.z));
            s.w = __fadd_rn(s.w, __fmul_rn(v.w, v.w));
        }
        rn_part[h * 128 + r] = __fadd_rn(__fadd_rn(s.x, s.y), __fadd_rn(s.z, s.w));
    }
    __syncthreads();
    if (tid < 128) rownorm[tid] = __fadd_rn(rn_part[tid], rn_part[128 + tid]);
    __syncthreads();

    double loss_acc = 0.0;
    int ksv[NUM_CB];
    int g = 0;

    float anorm[4];
#pragma unroll
    for (int rs = 0; rs < 4; ++rs)
        anorm[rs] = rownorm[rg * 32 + (rs >> 1) * 16 + (rs & 1) * 8 + gid];

    for (int cbi = 0; cbi < NUM_CB; ++cbi) {
        reinterpret_cast<float4*>(WN)[tid] =
            reinterpret_cast<const float4*>(g_wnorm + cbi * KCB)[tid];
        if (tid == 0) *cnt1 = 0;
        __syncthreads();

        unsigned long long b1[4], b2[4];
#pragma unroll
        for (int rs = 0; rs < 4; ++rs) { b1[rs] = ~0ull; b2[rs] = ~0ull; }

        for (int c = 0; c < CHUNKS_PER_CB; ++c, ++g) {
            float* Bcur  = (g & 1) ? B1 : B0;
            float* Bnext = (g & 1) ? B0 : B1;

            if (g + 1 < TILES) {
                const char* src = reinterpret_cast<const char*>(g_wf)
                                + (size_t)(g + 1) * BTILE_BYTES;
#pragma unroll
                for (int i = 0; i < 16; ++i) {
                    int f = tid + i * THREADS;
                    cp_async16(reinterpret_cast<char*>(Bnext) + (size_t)f * 16,
                               src + (size_t)f * 16);
                }
            }
            cp_commit();
            cp_wait1();
            __syncthreads();

            // ---- tf32 GEMM ----
            float d[2][4][4];
#pragma unroll
            for (int m = 0; m < 2; ++m)
#pragma unroll
                for (int nt = 0; nt < 4; ++nt)
#pragma unroll
                    for (int i = 0; i < 4; ++i) d[m][nt][i] = 0.f;

            const float4* Bf4 = reinterpret_cast<const float4*>(Bcur);

#pragma unroll 2
            for (int kt = 0; kt < 16; ++kt) {
                unsigned ah[2][4], al[2][4];
#pragma unroll
                for (int m = 0; m < 2; ++m) {
                    int r0 = rg * 32 + m * 16 + gid;
                    int k0 = kt * 8 + tig;
                    float a0 = A_s[r0 * APITCH + k0];
                    float a1 = A_s[(r0 + 8) * APITCH + k0];
                    float a2 = A_s[r0 * APITCH + k0 + 4];
                    float a3 = A_s[(r0 + 8) * APITCH + k0 + 4];
                    split_tf32(a0, ah[m][0], al[m][0]);
                    split_tf32(a1, ah[m][1], al[m][1]);
                    split_tf32(a2, ah[m][2], al[m][2]);
                    split_tf32(a3, ah[m][3], al[m][3]);
                }
                float4 bf[4];
#pragma unroll
                for (int nt = 0; nt < 4; ++nt)
                    bf[nt] = Bf4[((chh * 4 + nt) * 16 + kt) * 32 + lane];

#pragma unroll
                for (int nt = 0; nt < 4; ++nt)
#pragma unroll
                    for (int m = 0; m < 2; ++m)
                        mma8(d[m][nt], ah[m],
                             __float_as_uint(bf[nt].x), __float_as_uint(bf[nt].y));
#pragma unroll
                for (int nt = 0; nt < 4; ++nt)
#pragma unroll
                    for (int m = 0; m < 2; ++m)
                        mma8(d[m][nt], ah[m],
                             __float_as_uint(bf[nt].z), __float_as_uint(bf[nt].w));
#pragma unroll
                for (int nt = 0; nt < 4; ++nt)
#pragma unroll
                    for (int m = 0; m < 2; ++m)
                        mma8(d[m][nt], al[m],
                             __float_as_uint(bf[nt].x), __float_as_uint(bf[nt].y));
            }

            // ---- scores + per-thread top-2 ----
            float2 wn2[4];
            int cb0 = c * CHUNK;
#pragma unroll
            for (int nt = 0; nt < 4; ++nt)
                wn2[nt] = *reinterpret_cast<const float2*>(
                    WN + cb0 + (chh * 4 + nt) * 8 + 2 * tig);
#pragma unroll
            for (int m = 0; m < 2; ++m)
#pragma unroll
                for (int h = 0; h < 2; ++h) {
                    int rs = m * 2 + h;
                    float an = anorm[rs];
#pragma unroll
                    for (int nt = 0; nt < 4; ++nt) {
                        int col = cb0 + (chh * 4 + nt) * 8 + 2 * tig;
                        float s0 = __fadd_rn(__fadd_rn(an, -d[m][nt][2 * h]), wn2[nt].x);
                        float s1 = __fadd_rn(__fadd_rn(an, -d[m][nt][2 * h + 1]), wn2[nt].y);
                        unsigned long long k0 =
                            ((unsigned long long)sortf(s0) << 32) | (unsigned)col;
                        unsigned long long k1 =
                            ((unsigned long long)sortf(s1) << 32) | (unsigned)(col + 1);
                        top2_upd(k0, b1[rs], b2[rs]);
                        top2_upd(k1, b1[rs], b2[rs]);
                    }
                }
            __syncthreads();
        }

        // ---- store per-thread top-2 candidates (16 per row) ----
#pragma unroll
        for (int rs = 0; rs < 4; ++rs) {
            int row = rg * 32 + (rs >> 1) * 16 + (rs & 1) * 8 + gid;
            unsigned long long* cptr = CAND + (size_t)(row * 8 + chh * 4 + tig) * 2;
            cptr[0] = b1[rs];
            cptr[1] = b2[rs];
        }
        __syncthreads();

        // ---- per-row merge: global top-2, flag, provisional code ----
        if (tid < 128) {
            const unsigned long long* cr = CAND + tid * 16;
            unsigned long long s1 = ~0ull, s2 = ~0ull;
#pragma unroll
            for (int j = 0; j < 16; ++j) top2_upd(cr[j], s1, s2);
            float f1 = unsortf((unsigned)(s1 >> 32));
            float f2 = unsortf((unsigned)(s2 >> 32));
            float th = __fadd_rn(f1, EPS_GAP);
            int mode = 0;
            if (f2 < th) {
                mode = 1;
#pragma unroll
                for (int t = 0; t < 8; ++t) {
                    float fs = unsortf((unsigned)(cr[t * 2 + 1] >> 32));
                    if (fs < th) mode = 2;   // a thread may hide a 3rd near-tie
                }
            }
            rowmode[tid] = mode;
            kbest[cbi * M_TILE + tid] = (int)(unsigned)s1;
            if (mode == 1) { int p = atomicAdd(cnt1, 1); list1[p] = tid; }
        }
        __syncthreads();

        // ---- mode-1: 16-candidate exact rescue (one warp per row) ----
        int n1 = *cnt1;
        for (int i = wid; i < n1; i += 8) {
            int r = list1[i];
            unsigned long long key = (lane < 16) ? CAND[r * 16 + lane] : ~0ull;
            int code = (lane < 16) ? (int)(unsigned)key : 0;
            float an = rownorm[r];
            const float4* ar = reinterpret_cast<const float4*>(A_s + r * APITCH);
            const float4* wp = reinterpret_cast<const float4*>(
                cb + ((size_t)(cbi * KCB + code)) * DIM);
            float ddot = 0.f;
#pragma unroll 8
            for (int q = 0; q < 32; ++q) {
                float4 a = ar[q], w = wp[q];
                ddot = __fmaf_rn(a.x, w.x, ddot);
                ddot = __fmaf_rn(a.y, w.y, ddot);
                ddot = __fmaf_rn(a.z, w.z, ddot);
                ddot = __fmaf_rn(a.w, w.w, ddot);
            }
            float s = __fadd_rn(__fadd_rn(an, -2.0f * ddot), WN[code]);
            unsigned long long nk = (lane < 16)
                ? ((((unsigned long long)sortf(s)) << 32) | (unsigned)code) : ~0ull;
#pragma unroll
            for (int off = 16; off > 0; off >>= 1)
                nk = min(nk, __shfl_xor_sync(0xffffffffu, nk, off));
            if (lane == 0) kbest[cbi * M_TILE + r] = (int)(unsigned)nk;
        }
        __syncthreads();

        // ---- mode-2: full-1024 exact scan (rare) ----
        for (int r = 0; r < M_TILE; ++r) {
            if (rowmode[r] != 2) continue;
            float an = rownorm[r];
            const float4* ar = reinterpret_cast<const float4*>(A_s + r * APITCH);
            const float* wb = cb + ((size_t)(cbi * KCB + tid * 4)) * DIM;
            float dd[4] = {0.f, 0.f, 0.f, 0.f};
#pragma unroll 4
            for (int q = 0; q < 32; ++q) {
                float4 a = ar[q];
#pragma unroll
                for (int cc = 0; cc < 4; ++cc) {
                    float4 w = *reinterpret_cast<const float4*>(wb + cc * DIM + q * 4);
                    dd[cc] = __fmaf_rn(a.x, w.x, dd[cc]);
                    dd[cc] = __fmaf_rn(a.y, w.y, dd[cc]);
                    dd[cc] = __fmaf_rn(a.z, w.z, dd[cc]);
                    dd[cc] = __fmaf_rn(a.w, w.w, dd[cc]);
                }
            }
            unsigned long long m = ~0ull;
#pragma unroll
            for (int cc = 0; cc < 4; ++cc) {
                int code = tid * 4 + cc;
                float s = __fadd_rn(__fadd_rn(an, -2.0f * dd[cc]), WN[code]);
                unsigned long long key =
                    ((unsigned long long)sortf(s) << 32) | (unsigned)code;
                m = min(m, key);
            }
#pragma unroll
            for (int off = 16; off > 0; off >>= 1)
                m = min(m, __shfl_xor_sync(0xffffffffu, m, off));
            if (lane == 0) atomicMin(rk, m);
            __syncthreads();
            if (tid == 0) {
                kbest[cbi * M_TILE + r] = (int)(unsigned)(*rk);
                *rk = ~0ull;
            }
            __syncthreads();
        }

        // ---- commit codes ----
        if (tid < 128)
            out[(size_t)(row0 + tid) * NUM_CB + cbi] = (float)kbest[cbi * M_TILE + tid];
        __syncthreads();

        // ---- residual update, new row norms, loss ----
        {
            int r = tid & 127, h = tid >> 7;
            int k = kbest[cbi * M_TILE + r];
            const float4* wp = reinterpret_cast<const float4*>(
                cb + ((size_t)(cbi * KCB + k)) * DIM + h * 64);
            float4* ap = reinterpret_cast<float4*>(A_s + r * APITCH + h * 64);
            float4 s = make_float4(0.f, 0.f, 0.f, 0.f);
#pragma unroll
            for (int i = 0; i < 16; ++i) {
                float4 rv = ap[i], wv = wp[i], nr;
                nr.x = __fadd_rn(rv.x, -wv.x);
                nr.y = __fadd_rn(rv.y, -wv.y);
                nr.z = __fadd_rn(rv.z, -wv.z);
                nr.w = __fadd_rn(rv.w, -wv.w);
                ap[i] = nr;
                s.x = __fadd_rn(s.x, __fmul_rn(nr.x, nr.x));
                s.y = __fadd_rn(s.y, __fmul_rn(nr.y, nr.y));
                s.z = __fadd_rn(s.z, __fmul_rn(nr.z, nr.z));
                s.w = __fadd_rn(s.w, __fmul_rn(nr.w, nr.w));
            }
            float p = __fadd_rn(__fadd_rn(s.x, s.y), __fadd_rn(s.z, s.w));
            rn_part[h * 128 + r] = p;
            loss_acc += (double)p;
        }
        __syncthreads();
        if (tid < 128) rownorm[tid] = __fadd_rn(rn_part[tid], rn_part[128 + tid]);
        __syncthreads();
#pragma unroll
        for (int rs = 0; rs < 4; ++rs)
            anorm[rs] = rownorm[rg * 32 + (rs >> 1) * 16 + (rs & 1) * 8 + gid];
    }

    // ---- quantized output ----
    {
        int r = tid & 127, h = tid >> 7;
        int n = row0 + r;
#pragma unroll
        for (int c = 0; c < NUM_CB; ++c) ksv[c] = kbest[c * M_TILE + r];
#pragma unroll 4
        for (int d4 = 0; d4 < 16; ++d4) {
            int dd = h * 16 + d4;
            float4 q = make_float4(0.f, 0.f, 0.f, 0.f);
#pragma unroll
            for (int c = 0; c < NUM_CB; ++c) {
                float4 wv = reinterpret_cast<const float4*>(
                    cb + (size_t)(c * KCB + ksv[c]) * DIM)[dd];
                q.x = __fadd_rn(q.x, wv.x);
                q.y = __fadd_rn(q.y, wv.y);
                q.z = __fadd_rn(q.z, wv.z);
                q.w = __fadd_rn(q.w, wv.w);
            }
            float4 e = reinterpret_cast<const float4*>(emb + (size_t)n * DIM)[dd];
            float4 o;
            o.x = __fadd_rn(e.x, __fadd_rn(q.x, -e.x));
            o.y = __fadd_rn(e.y, __fadd_rn(q.y, -e.y));
            o.z = __fadd_rn(e.z, __fadd_rn(q.z, -e.z));
            o.w = __fadd_rn(e.w, __fadd_rn(q.w, -e.w));
            reinterpret_cast<float4*>(out + CODES_SZ + (size_t)n * DIM)[dd] = o;
        }
    }

    // ---- loss reduction ----
    double v = loss_acc;
#pragma unroll
    for (int off = 16; off > 0; off >>= 1)
        v += __shfl_down_sync(0xffffffffu, v, off);
    if ((tid & 31) == 0) atomicAdd(&g_loss, v);
}

__global__ void finalize_kernel(float* __restrict__ out) {
    out[CODES_SZ + QUANT_SZ] = (float)(g_loss / ((double)QUANT_SZ * (double)NUM_CB));
}

// ---------------------------------------------------------------------------
extern "C" void kernel_launch(void* const* d_in, const int* in_sizes, int n_in,
                              void* d_out, int out_size) {
    const float* emb = (const float*)d_in[0];   // [8,4096,128]
    const float* cb  = (const float*)d_in[1];   // [8,1024,128]
    float* out = (float*)d_out;

    cudaFuncSetAttribute(rvq_main, cudaFuncAttributeMaxDynamicSharedMemorySize,
                         SMEM_BYTES);

    wnorm_kernel<<<32, 256>>>(cb);
    wfrag_kernel<<<2048, 256>>>(cb);
    rvq_main<<<N_CTAS, THREADS, SMEM_BYTES>>>(emb, cb, out);
    finalize_kernel<<<1, 1>>>(out);
}

// round 17
// speedup vs baseline: 2.5400x; 2.5400x over previous
#include <cuda_runtime.h>
#include <cuda_bf16.h>
#include <cstdint>

// ---------------------------------------------------------------------------
// Residual VQ: B=8, T=4096, D=128, NUM_CB=8, K=1024   (N = 32768 rows)
// out (float32): [0,262144) codes [B,T,8]; [262144,+4194304) quantized; last = loss
//
// FFMA2 (fma.rn.f32x2) v3 — fine-grained tiles for wave packing:
//  - M_TILE=32 -> 1024 CTAs -> 7 vs 6.92 per SM = 1.2% imbalance (was 13.5%).
//  - per-thread 4 rows x 2 col-pairs; warp owns whole rows -> full-warp shfl
//    argmin. All score/dot/a_norm chains bitwise-identical to the proven R9.
//  - W pre-paired in global (g_wp, same layout/precompute as R9), cp.async
//    double-buffered 64KB chunks (128 codes).
// ---------------------------------------------------------------------------

#define N_ROWS   32768
#define DIM      128
#define NUM_CB   8
#define KCB      1024
#define M_TILE   32
#define APITCH   132                   // A row pitch (floats)
#define N_CTAS   (N_ROWS / M_TILE)     // 1024
#define CODES_SZ (N_ROWS * NUM_CB)     // 262144
#define QUANT_SZ (N_ROWS * DIM)        // 4194304
#define THREADS  256
#define CHUNK    128                   // codes per chunk
#define PAIRS    64                    // col pairs per chunk
#define CHUNKS_PER_CB 8
#define TILES    (NUM_CB * CHUNKS_PER_CB)   // 64
#define BTILE_FLOATS (DIM * CHUNK)     // 16384 floats = 64KB

// smem layout (floats)
#define SMF_A    0                                  // 32*132 = 4224
#define SMF_B0   (SMF_A + M_TILE * APITCH)          // 16384
#define SMF_B1   (SMF_B0 + BTILE_FLOATS)            // 16384
#define SMF_WN   (SMF_B1 + BTILE_FLOATS)            // 1024
#define SMF_RN   (SMF_WN + KCB)                     // 32   rownorm
#define SMF_RP   (SMF_RN + M_TILE)                  // 128  rn_part (4 quarters)
#define SMF_KB   (SMF_RP + 4 * M_TILE)              // 256 ints (kbest 8x32)
#define SMEM_FLOATS (SMF_KB + NUM_CB * M_TILE)
#define SMEM_BYTES  (SMEM_FLOATS * 4)               // ~153.7KB

__device__ double g_loss;
__device__ float  g_wnorm[NUM_CB * KCB];                       // 32KB
__device__ __align__(16) float2 g_wp[TILES * DIM * PAIRS];     // 4MB

// ---------------- helpers ----------------
__device__ __forceinline__ unsigned long long pack2(float lo, float hi) {
    unsigned long long r;
    asm("mov.b64 %0, {%1, %2};" : "=l"(r) : "f"(lo), "f"(hi));
    return r;
}
__device__ __forceinline__ float2 unpack2(unsigned long long v) {
    float2 f;
    asm("mov.b64 {%0, %1}, %2;" : "=f"(f.x), "=f"(f.y) : "l"(v));
    return f;
}
__device__ __forceinline__ void ffma2(unsigned long long& d,
                                      unsigned long long a,
                                      unsigned long long b) {
    asm("fma.rn.f32x2 %0, %1, %2, %0;" : "+l"(d) : "l"(a), "l"(b));
}
__device__ __forceinline__ float f4c(const float4& v, int c) {
    switch (c) { case 0: return v.x; case 1: return v.y; case 2: return v.z; default: return v.w; }
}
__device__ __forceinline__ unsigned sortf(float f) {
    unsigned u = __float_as_uint(f);
    return u ^ (((int)u >> 31) | 0x80000000u);
}
__device__ __forceinline__ void cp_async16(void* sdst, const void* gsrc) {
    unsigned saddr = (unsigned)__cvta_generic_to_shared(sdst);
    asm volatile("cp.async.cg.shared.global [%0], [%1], 16;\n" :: "r"(saddr), "l"(gsrc));
}
__device__ __forceinline__ void cp_commit() {
    asm volatile("cp.async.commit_group;\n");
}
__device__ __forceinline__ void cp_wait1() {
    asm volatile("cp.async.wait_group 1;\n");
}

// ---------------- precompute: wnorm + loss zero ----------------
__global__ void wnorm_kernel(const float* __restrict__ cb) {
    int k = blockIdx.x * blockDim.x + threadIdx.x;   // 0..8191
    if (blockIdx.x == 0 && threadIdx.x == 0) g_loss = 0.0;
    if (k >= NUM_CB * KCB) return;
    const float4* p = reinterpret_cast<const float4*>(cb + (size_t)k * DIM);
    float4 s = make_float4(0.f, 0.f, 0.f, 0.f);
#pragma unroll
    for (int i = 0; i < 32; ++i) {
        float4 v = p[i];
        s.x = __fadd_rn(s.x, __fmul_rn(v.x, v.x));
        s.y = __fadd_rn(s.y, __fmul_rn(v.y, v.y));
        s.z = __fadd_rn(s.z, __fmul_rn(v.z, v.z));
        s.w = __fadd_rn(s.w, __fmul_rn(v.w, v.w));
    }
    g_wnorm[k] = __fadd_rn(__fadd_rn(s.x, s.y), __fadd_rn(s.z, s.w));
}

// ---------------- precompute: paired W layout (identical to R9) ----------------
// g_wp[g][k][p] = (cb[cbi, chunk*128+2p, k], cb[cbi, chunk*128+2p+1, k])
__global__ void wpair_kernel(const float* __restrict__ cb) {
    int idx = blockIdx.x * 256 + threadIdx.x;      // 0..524287
    int g   = idx >> 13;                           // tile = cbi*8+chunk
    int rem = idx & 8191;
    int k   = rem >> 6;                            // 0..127
    int p   = rem & 63;                            // 0..63
    int cbi = g >> 3, chunk = g & 7;
    int code0 = chunk * CHUNK + 2 * p;
    const float* base = cb + ((size_t)(cbi * KCB + code0)) * DIM + k;
    float2 v;
    v.x = base[0];
    v.y = base[DIM];
    g_wp[idx] = v;
}

// ---------------- main kernel ----------------
__global__ void __launch_bounds__(THREADS, 1)
rvq_main(const float* __restrict__ emb, const float* __restrict__ cb,
         float* __restrict__ out) {
    extern __shared__ float sm[];
    float* A_s     = sm + SMF_A;
    float* B0      = sm + SMF_B0;
    float* B1      = sm + SMF_B1;
    float* WN      = sm + SMF_WN;
    float* rownorm = sm + SMF_RN;
    float* rn_part = sm + SMF_RP;
    int*   kbest   = reinterpret_cast<int*>(sm + SMF_KB);

    const int tid = threadIdx.x;
    const int tx  = tid & 31;          // lane; col-pair group (pairs tx, tx+32)
    const int ty  = tid >> 5;          // warp id 0..7; rows ty + 8j, j=0..3
    const int row0 = blockIdx.x * M_TILE;

    // ---- load A tile (embeddings), pitch 132 ----
    {
        const float4* ev = reinterpret_cast<const float4*>(emb + (size_t)row0 * DIM);
#pragma unroll
        for (int i = 0; i < 4; ++i) {
            int f = tid + i * THREADS;           // 0..1023
            int r = f >> 5, d4 = f & 31;
            reinterpret_cast<float4*>(A_s)[r * (APITCH / 4) + d4] = ev[f];
        }
    }

    // ---- prefetch first B tile (paired layout, linear 64KB) ----
    {
        const char* src = reinterpret_cast<const char*>(g_wp);
#pragma unroll
        for (int i = 0; i < 16; ++i) {
            int f = tid + i * THREADS;           // 16B unit, 4096 total
            cp_async16(reinterpret_cast<char*>(B0) + (size_t)f * 16,
                       src + (size_t)f * 16);
        }
        cp_commit();
    }
    __syncthreads();

    // ---- initial row norms ||e||^2 (quarter partials, chain as R9) ----
    if (tid < 128) {
        int r = tid & 31, h = tid >> 5;          // h = 0..3
        const float4* a = reinterpret_cast<const float4*>(A_s + r * APITCH + h * 32);
        float4 s = make_float4(0.f, 0.f, 0.f, 0.f);
#pragma unroll
        for (int i = 0; i < 8; ++i) {
            float4 v = a[i];
            s.x = __fadd_rn(s.x, __fmul_rn(v.x, v.x));
            s.y = __fadd_rn(s.y, __fmul_rn(v.y, v.y));
            s.z = __fadd_rn(s.z, __fmul_rn(v.z, v.z));
            s.w = __fadd_rn(s.w, __fmul_rn(v.w, v.w));
        }
        rn_part[h * 32 + r] = __fadd_rn(__fadd_rn(s.x, s.y), __fadd_rn(s.z, s.w));
    }
    __syncthreads();
    if (tid < 32)
        rownorm[tid] = __fadd_rn(__fadd_rn(rn_part[tid], rn_part[32 + tid]),
                                 __fadd_rn(rn_part[64 + tid], rn_part[96 + tid]));
    __syncthreads();

    double loss_acc = 0.0;
    int g = 0;   // global tile index 0..63

    for (int cbi = 0; cbi < NUM_CB; ++cbi) {
        // wn for this codebook into smem (1024 floats)
        reinterpret_cast<float4*>(WN)[tid] =
            reinterpret_cast<const float4*>(g_wnorm + cbi * KCB)[tid];
        __syncthreads();

        unsigned long long best[4];
#pragma unroll
        for (int j = 0; j < 4; ++j) best[j] = ~0ull;

        for (int chunk = 0; chunk < CHUNKS_PER_CB; ++chunk, ++g) {
            float* Bcur  = (g & 1) ? B1 : B0;
            float* Bnext = (g & 1) ? B0 : B1;

            // prefetch next tile
            if (g + 1 < TILES) {
                const char* src = reinterpret_cast<const char*>(g_wp)
                                + (size_t)(g + 1) * (BTILE_FLOATS * 4);
#pragma unroll
                for (int i = 0; i < 16; ++i) {
                    int f = tid + i * THREADS;
                    cp_async16(reinterpret_cast<char*>(Bnext) + (size_t)f * 16,
                               src + (size_t)f * 16);
                }
            }
            cp_commit();
            cp_wait1();
            __syncthreads();

            // ---- GEMM: acc[j][i2] packed f32x2 over adjacent column pairs ----
            unsigned long long acc[4][2];
#pragma unroll
            for (int j = 0; j < 4; ++j)
#pragma unroll
                for (int i2 = 0; i2 < 2; ++i2) acc[j][i2] = 0ull;

            const float* a0 = A_s + ty * APITCH;

#pragma unroll 4
            for (int kk4 = 0; kk4 < 32; ++kk4) {
                float4 av[4];
#pragma unroll
                for (int j = 0; j < 4; ++j)
                    av[j] = *reinterpret_cast<const float4*>(
                        a0 + j * (8 * APITCH) + kk4 * 4);
#pragma unroll
                for (int dk = 0; dk < 4; ++dk) {
                    const unsigned long long* brow =
                        reinterpret_cast<const unsigned long long*>(
                            Bcur + (kk4 * 4 + dk) * CHUNK);
                    unsigned long long b2[2];
#pragma unroll
                    for (int i2 = 0; i2 < 2; ++i2)
                        b2[i2] = brow[tx + 32 * i2];
#pragma unroll
                    for (int j = 0; j < 4; ++j) {
                        float a = f4c(av[j], dk);
                        unsigned long long a2 = pack2(a, a);
#pragma unroll
                        for (int i2 = 0; i2 < 2; ++i2)
                            ffma2(acc[j][i2], a2, b2[i2]);
                    }
                }
            }

            // ---- scores + running argmin (full-warp reduce per row) ----
#pragma unroll
            for (int j = 0; j < 4; ++j) {
                int row = ty + 8 * j;
                float a = rownorm[row];
                unsigned long long m = ~0ull;
#pragma unroll
                for (int i2 = 0; i2 < 2; ++i2) {
                    float2 d = unpack2(acc[j][i2]);
                    int p = tx + 32 * i2;
                    int c0 = chunk * CHUNK + 2 * p;
                    float2 w2 = *reinterpret_cast<const float2*>(WN + c0);
                    float s0 = __fadd_rn(__fadd_rn(a, -2.0f * d.x), w2.x);
                    float s1 = __fadd_rn(__fadd_rn(a, -2.0f * d.y), w2.y);
                    unsigned long long k0 = ((unsigned long long)sortf(s0) << 32) | (unsigned)c0;
                    unsigned long long k1 = ((unsigned long long)sortf(s1) << 32) | (unsigned)(c0 + 1);
                    m = min(m, k0);
                    m = min(m, k1);
                }
#pragma unroll
                for (int off = 1; off < 32; off <<= 1) {
                    unsigned long long o = __shfl_xor_sync(0xffffffffu, m, off);
                    m = min(m, o);
                }
                best[j] = min(best[j], m);
            }
            __syncthreads();   // Bcur safe to overwrite next iteration
        }

        // ---- commit codes + kbest ----
        if (tx == 0) {
#pragma unroll
            for (int j = 0; j < 4; ++j) {
                int row = ty + 8 * j;
                int k = (int)(unsigned)best[j];
                kbest[cbi * M_TILE + row] = k;
                out[(size_t)(row0 + row) * NUM_CB + cbi] = (float)k;
            }
        }
        __syncthreads();

        // ---- residual update (quarters), new row norms, loss (chain as R9) ----
        if (tid < 128) {
            int r = tid & 31, h = tid >> 5;
            int k = kbest[cbi * M_TILE + r];
            const float4* wp = reinterpret_cast<const float4*>(
                cb + ((size_t)(cbi * KCB + k)) * DIM + h * 32);
            float4* ap = reinterpret_cast<float4*>(A_s + r * APITCH + h * 32);
            float4 s = make_float4(0.f, 0.f, 0.f, 0.f);
#pragma unroll
            for (int i = 0; i < 8; ++i) {
                float4 rv = ap[i], wv = wp[i], nr;
                nr.x = __fadd_rn(rv.x, -wv.x);
                nr.y = __fadd_rn(rv.y, -wv.y);
                nr.z = __fadd_rn(rv.z, -wv.z);
                nr.w = __fadd_rn(rv.w, -wv.w);
                ap[i] = nr;
                s.x = __fadd_rn(s.x, __fmul_rn(nr.x, nr.x));
                s.y = __fadd_rn(s.y, __fmul_rn(nr.y, nr.y));
                s.z = __fadd_rn(s.z, __fmul_rn(nr.z, nr.z));
                s.w = __fadd_rn(s.w, __fmul_rn(nr.w, nr.w));
            }
            float p = __fadd_rn(__fadd_rn(s.x, s.y), __fadd_rn(s.z, s.w));
            rn_part[h * 32 + r] = p;
            loss_acc += (double)p;   // loss term = ||r - w||^2 = ||r_new||^2
        }
        __syncthreads();
        if (tid < 32)
            rownorm[tid] = __fadd_rn(__fadd_rn(rn_part[tid], rn_part[32 + tid]),
                                     __fadd_rn(rn_part[64 + tid], rn_part[96 + tid]));
        __syncthreads();
    }

    // ---- quantized output: q = sum_c w_c (in order), out = e + (q - e) ----
    if (tid < 128) {
        int r = tid & 31, h = tid >> 5;
        int n = row0 + r;
        int ks[NUM_CB];
#pragma unroll
        for (int c = 0; c < NUM_CB; ++c) ks[c] = kbest[c * M_TILE + r];
#pragma unroll
        for (int i = 0; i < 8; ++i) {
            int d4 = h * 8 + i;
            float4 q = make_float4(0.f, 0.f, 0.f, 0.f);
#pragma unroll
            for (int c = 0; c < NUM_CB; ++c) {
                float4 wv = reinterpret_cast<const float4*>(
                    cb + (size_t)(c * KCB + ks[c]) * DIM)[d4];
                q.x = __fadd_rn(q.x, wv.x);
                q.y = __fadd_rn(q.y, wv.y);
                q.z = __fadd_rn(q.z, wv.z);
                q.w = __fadd_rn(q.w, wv.w);
            }
            float4 e = reinterpret_cast<const float4*>(emb + (size_t)n * DIM)[d4];
            float4 o;
            o.x = __fadd_rn(e.x, __fadd_rn(q.x, -e.x));
            o.y = __fadd_rn(e.y, __fadd_rn(q.y, -e.y));
            o.z = __fadd_rn(e.z, __fadd_rn(q.z, -e.z));
            o.w = __fadd_rn(e.w, __fadd_rn(q.w, -e.w));
            reinterpret_cast<float4*>(out + CODES_SZ + (size_t)n * DIM)[d4] = o;
        }
    }

    // ---- loss reduction ----
    double v = loss_acc;
#pragma unroll
    for (int off = 16; off > 0; off >>= 1)
        v += __shfl_down_sync(0xffffffffu, v, off);
    if ((tid & 31) == 0) atomicAdd(&g_loss, v);
}

__global__ void finalize_kernel(float* __restrict__ out) {
    out[CODES_SZ + QUANT_SZ] = (float)(g_loss / ((double)QUANT_SZ * (double)NUM_CB));
}

// ---------------------------------------------------------------------------
extern "C" void kernel_launch(void* const* d_in, const int* in_sizes, int n_in,
                              void* d_out, int out_size) {
    const float* emb = (const float*)d_in[0];   // [8,4096,128]
    const float* cb  = (const float*)d_in[1];   // [8,1024,128]
    float* out = (float*)d_out;

    cudaFuncSetAttribute(rvq_main, cudaFuncAttributeMaxDynamicSharedMemorySize,
                         SMEM_BYTES);

    wnorm_kernel<<<32, 256>>>(cb);
    wpair_kernel<<<2048, 256>>>(cb);
    rvq_main<<<N_CTAS, THREADS, SMEM_BYTES>>>(emb, cb, out);
    finalize_kernel<<<1, 1>>>(out);
}